// round 7
// baseline (speedup 1.0000x reference)
#include <cuda_runtime.h>
#include <cuda_fp16.h>
#include <stdint.h>

#define IN_F    768
#define HID     64
#define MTILE   256
#define NCHUNK  12
#define THREADS 256
#define NSTEP1  48           // 768/16 k-steps for layer 1
#define NSTEP2  4            // 64/16 for layer 2

// ---------------- device scratch (no allocations allowed) ----------------
__device__ float g_w1d[HID * IN_F];            // dense W1^T [n][k]
__device__ float g_w2d[HID * HID];             // dense W2^T [n][k]
__device__ uint4 g_w1f[NSTEP1 * 8 * 32];       // B-fragments: (main b0,b1, resid b0,b1)
__device__ uint4 g_w2f[NSTEP2 * 8 * 32];
__device__ float g_w3[HID];

__device__ __forceinline__ uint32_t sw128(uint32_t a) { return a ^ ((a >> 3) & 0x70u); }

static __device__ __forceinline__ void mma16816(float* d, const uint32_t* a,
                                                uint32_t b0, uint32_t b1) {
    asm volatile(
        "mma.sync.aligned.m16n8k16.row.col.f32.f16.f16.f32 "
        "{%0,%1,%2,%3}, {%4,%5,%6,%7}, {%8,%9}, {%0,%1,%2,%3};"
        : "+f"(d[0]), "+f"(d[1]), "+f"(d[2]), "+f"(d[3])
        : "r"(a[0]), "r"(a[1]), "r"(a[2]), "r"(a[3]), "r"(b0), "r"(b1));
}
static __device__ __forceinline__ void ldmx4(uint32_t* a, uint32_t addr) {
    asm volatile("ldmatrix.sync.aligned.m8n8.x4.shared.b16 {%0,%1,%2,%3}, [%4];"
                 : "=r"(a[0]), "=r"(a[1]), "=r"(a[2]), "=r"(a[3]) : "r"(addr));
}
static __device__ __forceinline__ uint32_t pkh(__half a, __half b) {
    __half2 h = __halves2half2(a, b);
    return *reinterpret_cast<uint32_t*>(&h);
}

// ---------------- prep: zero -> scatter -> pack fragments ----------------
__global__ void zero_kernel() {
    const int t = blockIdx.x * blockDim.x + threadIdx.x;
    const int n = gridDim.x * blockDim.x;
    for (int i = t; i < HID * IN_F; i += n) g_w1d[i] = 0.f;
    for (int i = t; i < HID * HID;  i += n) g_w2d[i] = 0.f;
    for (int i = t; i < HID;        i += n) g_w3[i]  = 0.f;
}

__global__ void scatter_kernel(const int* __restrict__ idx1, const float* __restrict__ val1, int nnz1,
                               const int* __restrict__ idx2, const float* __restrict__ val2, int nnz2,
                               const int* __restrict__ idx3, const float* __restrict__ val3, int nnz3)
{
    const int t = blockIdx.x * blockDim.x + threadIdx.x;
    const int n = gridDim.x * blockDim.x;
    // idx layout [2,nnz]: rows then cols. dense is [n(col)][k(row)].
    for (int i = t; i < nnz1; i += n)
        atomicAdd(&g_w1d[idx1[nnz1 + i] * IN_F + idx1[i]], val1[i]);
    for (int i = t; i < nnz2; i += n)
        atomicAdd(&g_w2d[idx2[nnz2 + i] * HID + idx2[i]], val2[i]);
    for (int i = t; i < nnz3; i += n)
        atomicAdd(&g_w3[idx3[i]], val3[i]);
}

__global__ void pack_kernel() {
    const int tid = threadIdx.x;
    if (blockIdx.x < NSTEP1) {                 // one block per k-step of W1
        const int s    = blockIdx.x;
        const int nb   = tid >> 5;
        const int lane = tid & 31;
        const int k0 = s * 16 + (lane & 3) * 2;
        const int n  = nb * 8 + (lane >> 2);
        const float m0 = g_w1d[n * IN_F + k0];
        const float m1 = g_w1d[n * IN_F + k0 + 1];
        const float m2 = g_w1d[n * IN_F + k0 + 8];
        const float m3 = g_w1d[n * IN_F + k0 + 9];
        const __half h0 = __float2half_rn(m0), h1 = __float2half_rn(m1);
        const __half h2 = __float2half_rn(m2), h3 = __float2half_rn(m3);
        uint4 u;
        u.x = pkh(h0, h1);
        u.y = pkh(h2, h3);
        u.z = pkh(__float2half_rn(m0 - __half2float(h0)), __float2half_rn(m1 - __half2float(h1)));
        u.w = pkh(__float2half_rn(m2 - __half2float(h2)), __float2half_rn(m3 - __half2float(h3)));
        g_w1f[(s * 8 + nb) * 32 + lane] = u;
    } else {                                   // last block packs all of W2
        for (int j = tid; j < NSTEP2 * 8 * 32; j += THREADS) {
            const int s    = j >> 8;
            const int nb   = (j >> 5) & 7;
            const int lane = j & 31;
            const int k0 = s * 16 + (lane & 3) * 2;
            const int n  = nb * 8 + (lane >> 2);
            const float m0 = g_w2d[n * HID + k0];
            const float m1 = g_w2d[n * HID + k0 + 1];
            const float m2 = g_w2d[n * HID + k0 + 8];
            const float m3 = g_w2d[n * HID + k0 + 9];
            const __half h0 = __float2half_rn(m0), h1 = __float2half_rn(m1);
            const __half h2 = __float2half_rn(m2), h3 = __float2half_rn(m3);
            uint4 u;
            u.x = pkh(h0, h1);
            u.y = pkh(h2, h3);
            u.z = pkh(__float2half_rn(m0 - __half2float(h0)), __float2half_rn(m1 - __half2float(h1)));
            u.w = pkh(__float2half_rn(m2 - __half2float(h2)), __float2half_rn(m3 - __half2float(h3)));
            g_w2f[(s * 8 + nb) * 32 + lane] = u;
        }
    }
}

// ---------------- smem layout (bytes) ----------------
#define SM_B1   0
#define SM_B2   256
#define SM_W3   512
#define SM_X    1024                  // 2 x 32768 (x chunk: 256 rows x 128B fp16, SW128)
#define SM_H1   66560                 // 32768     (h1: 256 rows x 128B fp16, SW128)
#define SMEM_TOTAL 99328

extern __shared__ unsigned char smem[];

__global__ __launch_bounds__(THREADS, 2)
void mma_kernel(const float* __restrict__ x,
                const float* __restrict__ b1,
                const float* __restrict__ b2,
                const float* __restrict__ b3,
                float* __restrict__ out, int batch)
{
    uint32_t sb;
    asm("{ .reg .u64 t; cvta.to.shared.u64 t, %1; cvt.u32.u64 %0, t; }" : "=r"(sb) : "l"(smem));
    const int tid  = threadIdx.x;
    const int w    = tid >> 5;
    const int lane = tid & 31;
    const int row0 = blockIdx.x * MTILE;
    const bool full = (row0 + MTILE) <= batch;

    if (tid < HID) {
        ((float*)(smem + SM_B1))[tid] = __ldg(b1 + tid);
        ((float*)(smem + SM_B2))[tid] = __ldg(b2 + tid);
        ((float*)(smem + SM_W3))[tid] = g_w3[tid];
    }

    // coalesced staging map: thread -> fixed col4, rows j*16 + (tid>>4)
    const int c4   = tid & 15;
    const int rsub = tid >> 4;

    // ldmatrix A-address bases for the warp's two 16-row stripes
    const uint32_t ab0 = (uint32_t)((      w * 16 + (lane & 15)) * 128 + (lane >> 4) * 16);
    const uint32_t ab1 = (uint32_t)((128 + w * 16 + (lane & 15)) * 128 + (lane >> 4) * 16);

    float acc0[32], acc1[32];
    #pragma unroll
    for (int i = 0; i < 32; ++i) { acc0[i] = 0.f; acc1[i] = 0.f; }

    uint2 xr[8];   // staged half-chunk (8 row-groups), held in registers

    // ---- LDG+convert one half (h=0/1) of chunk k into regs ----
    auto ldg_half = [&](int k, int h, uint2* r) {
        #pragma unroll
        for (int j = 0; j < 8; ++j) {
            const int row = (h * 8 + j) * 16 + rsub;
            float4 v = make_float4(0.f, 0.f, 0.f, 0.f);
            if (full || (row0 + row) < batch)
                v = __ldg(reinterpret_cast<const float4*>(x) +
                          ((size_t)(row0 + row) * (IN_F / 4) + k * 16 + c4));
            r[j].x = pkh(__float2half_rn(v.x), __float2half_rn(v.y));
            r[j].y = pkh(__float2half_rn(v.z), __float2half_rn(v.w));
        }
    };
    // ---- store a staged half to smem buffer p ----
    auto sts_half = [&](int h, int p, const uint2* r) {
        unsigned char* dst = smem + SM_X + p * 32768;
        #pragma unroll
        for (int j = 0; j < 8; ++j) {
            const int row = (h * 8 + j) * 16 + rsub;
            *(uint2*)(dst + sw128((uint32_t)(row * 128 + c4 * 8))) = r[j];
        }
    };
    // ---- one k-step (s) of layer-1 MMAs on buffer p of chunk k ----
    auto compute_step = [&](int k, int p, int s) {
        uint32_t a0[4], a1[4];
        const uint32_t xb = sb + SM_X + p * 32768;
        ldmx4(a0, xb + sw128(ab0 + s * 32));
        ldmx4(a1, xb + sw128(ab1 + s * 32));
        const uint4* wf = g_w1f + (size_t)(k * 4 + s) * 256 + lane;
        #pragma unroll
        for (int nb = 0; nb < 8; ++nb) {
            const uint4 f = __ldg(wf + nb * 32);
            mma16816(acc0 + nb * 4, a0, f.x, f.y);
            mma16816(acc0 + nb * 4, a0, f.z, f.w);
            mma16816(acc1 + nb * 4, a1, f.x, f.y);
            mma16816(acc1 + nb * 4, a1, f.z, f.w);
        }
    };

    // ---- prologue: stage chunk 0 ----
    ldg_half(0, 0, xr); sts_half(0, 0, xr);
    ldg_half(0, 1, xr); sts_half(1, 0, xr);
    __syncthreads();

    // ---- mainloop: LDGs for k+1 issued before/mid compute, STS after ----
    for (int k = 0; k < NCHUNK; ++k) {
        const int p = k & 1;
        const bool more = (k + 1) < NCHUNK;
        if (more) ldg_half(k + 1, 0, xr);          // covered by s0,s1 MMAs
        compute_step(k, p, 0);
        compute_step(k, p, 1);
        if (more) { sts_half(0, p ^ 1, xr); ldg_half(k + 1, 1, xr); }
        compute_step(k, p, 2);
        compute_step(k, p, 3);
        if (more) sts_half(1, p ^ 1, xr);
        __syncthreads();
    }

    // ---- epilogue 1: h1 = relu(acc + b1) -> fp16 SW128 smem (both stripes) ----
    {
        const float* b1s = (const float*)(smem + SM_B1);
        const int r = lane >> 2;
        const uint32_t cofs = (lane & 3) * 4;
        #pragma unroll
        for (int st = 0; st < 2; ++st) {
            const float* ac = st ? acc1 : acc0;
            const int R = st * 128 + w * 16 + r;
            #pragma unroll
            for (int nb = 0; nb < 8; ++nb) {
                const int n = nb * 8 + (lane & 3) * 2;
                const float ba = b1s[n], bb = b1s[n + 1];
                const float v0 = fmaxf(ac[nb * 4 + 0] + ba, 0.f);
                const float v1 = fmaxf(ac[nb * 4 + 1] + bb, 0.f);
                const float v2 = fmaxf(ac[nb * 4 + 2] + ba, 0.f);
                const float v3 = fmaxf(ac[nb * 4 + 3] + bb, 0.f);
                *(uint32_t*)(smem + SM_H1 + sw128((uint32_t)(R * 128)       + nb * 16 + cofs)) =
                    pkh(__float2half_rn(v0), __float2half_rn(v1));
                *(uint32_t*)(smem + SM_H1 + sw128((uint32_t)((R + 8) * 128) + nb * 16 + cofs)) =
                    pkh(__float2half_rn(v2), __float2half_rn(v3));
            }
        }
    }
    __syncthreads();

    // ---- layer-2 GEMM (K=64) ----
    float ac20[32], ac21[32];
    #pragma unroll
    for (int i = 0; i < 32; ++i) { ac20[i] = 0.f; ac21[i] = 0.f; }
    #pragma unroll
    for (int s = 0; s < 4; ++s) {
        uint32_t a0[4], a1[4];
        ldmx4(a0, sb + SM_H1 + sw128(ab0 + s * 32));
        ldmx4(a1, sb + SM_H1 + sw128(ab1 + s * 32));
        const uint4* wf = g_w2f + (size_t)s * 256 + lane;
        #pragma unroll
        for (int nb = 0; nb < 8; ++nb) {
            const uint4 f = __ldg(wf + nb * 32);
            mma16816(ac20 + nb * 4, a0, f.x, f.y);
            mma16816(ac20 + nb * 4, a0, f.z, f.w);
            mma16816(ac21 + nb * 4, a1, f.x, f.y);
            mma16816(ac21 + nb * 4, a1, f.z, f.w);
        }
    }

    // ---- epilogue 2: out = relu(ac2 + b2) . w3 + b3 ----
    {
        const float* b2s = (const float*)(smem + SM_B2);
        const float* w3s = (const float*)(smem + SM_W3);
        const float b3v = __ldg(b3);
        #pragma unroll
        for (int st = 0; st < 2; ++st) {
            const float* ac = st ? ac21 : ac20;
            float pA = 0.f, pB = 0.f;
            #pragma unroll
            for (int nb = 0; nb < 8; ++nb) {
                const int n = nb * 8 + (lane & 3) * 2;
                const float ba = b2s[n],  bb = b2s[n + 1];
                const float wa = w3s[n],  wb = w3s[n + 1];
                pA += fmaxf(ac[nb * 4 + 0] + ba, 0.f) * wa
                    + fmaxf(ac[nb * 4 + 1] + bb, 0.f) * wb;
                pB += fmaxf(ac[nb * 4 + 2] + ba, 0.f) * wa
                    + fmaxf(ac[nb * 4 + 3] + bb, 0.f) * wb;
            }
            pA += __shfl_xor_sync(0xffffffffu, pA, 1);
            pA += __shfl_xor_sync(0xffffffffu, pA, 2);
            pB += __shfl_xor_sync(0xffffffffu, pB, 1);
            pB += __shfl_xor_sync(0xffffffffu, pB, 2);
            if ((lane & 3) == 0) {
                const int rA = row0 + st * 128 + w * 16 + (lane >> 2);
                if (rA < batch)     out[rA]     = pA + b3v;
                if (rA + 8 < batch) out[rA + 8] = pB + b3v;
            }
        }
    }
}

// ---------------------------------------------------------------------------
extern "C" void kernel_launch(void* const* d_in, const int* in_sizes, int n_in,
                              void* d_out, int out_size)
{
    const float* x    = (const float*)d_in[0];
    const int*   idx1 = (const int*)  d_in[1];
    const float* val1 = (const float*)d_in[2];
    const float* b1   = (const float*)d_in[3];
    const int*   idx2 = (const int*)  d_in[4];
    const float* val2 = (const float*)d_in[5];
    const float* b2   = (const float*)d_in[6];
    const int*   idx3 = (const int*)  d_in[7];
    const float* val3 = (const float*)d_in[8];
    const float* b3   = (const float*)d_in[9];

    const int nnz1  = in_sizes[1] / 2;
    const int nnz2  = in_sizes[4] / 2;
    const int nnz3  = in_sizes[7] / 2;
    const int batch = in_sizes[0] / IN_F;

    cudaFuncSetAttribute(mma_kernel, cudaFuncAttributeMaxDynamicSharedMemorySize, SMEM_TOTAL);

    zero_kernel<<<64, 256>>>();
    scatter_kernel<<<32, 256>>>(idx1, val1, nnz1, idx2, val2, nnz2, idx3, val3, nnz3);
    pack_kernel<<<NSTEP1 + 1, THREADS>>>();

    const int blocks = (batch + MTILE - 1) / MTILE;
    mma_kernel<<<blocks, THREADS, SMEM_TOTAL>>>(x, b1, b2, b3, (float*)d_out, batch);
}

// round 8
// speedup vs baseline: 1.4088x; 1.4088x over previous
#include <cuda_runtime.h>
#include <cuda_fp16.h>
#include <stdint.h>

#define IN_F    768
#define HID     64
#define MTILE   256
#define THREADS 256
#define NSTEP1  48           // 768/16 k-steps for layer 1
#define NSTEP2  4            // 64/16 for layer 2

// ---------------- device scratch (no allocations allowed) ----------------
__device__ float g_w1d[HID * IN_F];            // dense W1^T [n][k]
__device__ float g_w2d[HID * HID];             // dense W2^T [n][k]
__device__ uint4 g_w1f[NSTEP1 * 8 * 32];       // B-fragments: (main b0,b1, resid b0,b1)
__device__ uint4 g_w2f[NSTEP2 * 8 * 32];
__device__ float g_w3[HID];

static __device__ __forceinline__ void mma16816(float* d, const uint32_t* a,
                                                uint32_t b0, uint32_t b1) {
    asm volatile(
        "mma.sync.aligned.m16n8k16.row.col.f32.f16.f16.f32 "
        "{%0,%1,%2,%3}, {%4,%5,%6,%7}, {%8,%9}, {%0,%1,%2,%3};"
        : "+f"(d[0]), "+f"(d[1]), "+f"(d[2]), "+f"(d[3])
        : "r"(a[0]), "r"(a[1]), "r"(a[2]), "r"(a[3]), "r"(b0), "r"(b1));
}
static __device__ __forceinline__ uint32_t pkh(__half a, __half b) {
    __half2 h = __halves2half2(a, b);
    return *reinterpret_cast<uint32_t*>(&h);
}

// ---------------- prep: zero -> scatter -> pack fragments (validated) ------
__global__ void zero_kernel() {
    const int t = blockIdx.x * blockDim.x + threadIdx.x;
    const int n = gridDim.x * blockDim.x;
    for (int i = t; i < HID * IN_F; i += n) g_w1d[i] = 0.f;
    for (int i = t; i < HID * HID;  i += n) g_w2d[i] = 0.f;
    for (int i = t; i < HID;        i += n) g_w3[i]  = 0.f;
}

__global__ void scatter_kernel(const int* __restrict__ idx1, const float* __restrict__ val1, int nnz1,
                               const int* __restrict__ idx2, const float* __restrict__ val2, int nnz2,
                               const int* __restrict__ idx3, const float* __restrict__ val3, int nnz3)
{
    const int t = blockIdx.x * blockDim.x + threadIdx.x;
    const int n = gridDim.x * blockDim.x;
    // idx layout [2,nnz]: rows then cols. dense is [n(col)][k(row)].
    for (int i = t; i < nnz1; i += n)
        atomicAdd(&g_w1d[idx1[nnz1 + i] * IN_F + idx1[i]], val1[i]);
    for (int i = t; i < nnz2; i += n)
        atomicAdd(&g_w2d[idx2[nnz2 + i] * HID + idx2[i]], val2[i]);
    for (int i = t; i < nnz3; i += n)
        atomicAdd(&g_w3[idx3[i]], val3[i]);
}

__global__ void pack_kernel() {
    const int tid = threadIdx.x;
    if (blockIdx.x < NSTEP1) {                 // one block per k-step of W1
        const int s    = blockIdx.x;
        const int nb   = tid >> 5;
        const int lane = tid & 31;
        const int k0 = s * 16 + (lane & 3) * 2;
        const int n  = nb * 8 + (lane >> 2);
        const float m0 = g_w1d[n * IN_F + k0];
        const float m1 = g_w1d[n * IN_F + k0 + 1];
        const float m2 = g_w1d[n * IN_F + k0 + 8];
        const float m3 = g_w1d[n * IN_F + k0 + 9];
        const __half h0 = __float2half_rn(m0), h1 = __float2half_rn(m1);
        const __half h2 = __float2half_rn(m2), h3 = __float2half_rn(m3);
        uint4 u;
        u.x = pkh(h0, h1);
        u.y = pkh(h2, h3);
        u.z = pkh(__float2half_rn(m0 - __half2float(h0)), __float2half_rn(m1 - __half2float(h1)));
        u.w = pkh(__float2half_rn(m2 - __half2float(h2)), __float2half_rn(m3 - __half2float(h3)));
        g_w1f[(s * 8 + nb) * 32 + lane] = u;
    } else {                                   // last block packs all of W2
        for (int j = tid; j < NSTEP2 * 8 * 32; j += THREADS) {
            const int s    = j >> 8;
            const int nb   = (j >> 5) & 7;
            const int lane = j & 31;
            const int k0 = s * 16 + (lane & 3) * 2;
            const int n  = nb * 8 + (lane >> 2);
            const float m0 = g_w2d[n * HID + k0];
            const float m1 = g_w2d[n * HID + k0 + 1];
            const float m2 = g_w2d[n * HID + k0 + 8];
            const float m3 = g_w2d[n * HID + k0 + 9];
            const __half h0 = __float2half_rn(m0), h1 = __float2half_rn(m1);
            const __half h2 = __float2half_rn(m2), h3 = __float2half_rn(m3);
            uint4 u;
            u.x = pkh(h0, h1);
            u.y = pkh(h2, h3);
            u.z = pkh(__float2half_rn(m0 - __half2float(h0)), __float2half_rn(m1 - __half2float(h1)));
            u.w = pkh(__float2half_rn(m2 - __half2float(h2)), __float2half_rn(m3 - __half2float(h3)));
            g_w2f[(s * 8 + nb) * 32 + lane] = u;
        }
    }
}

// ---------------------------------------------------------------------------
// Main kernel: fully register-resident, NO shared memory, NO __syncthreads.
// Warp w owns rows {w*16..+15} and {128+w*16..+15}. A-fragments loaded
// directly from global fp32 (each LDG.64 = 8 rows x 32B contiguous = perfectly
// coalesced), converted in regs. h1 stays in registers (D-frag layout == next
// A-frag layout). Warps run free; latency hidden by 16 independent warps/SM.
// ---------------------------------------------------------------------------
__global__ __launch_bounds__(THREADS, 2)
void mma_kernel(const float* __restrict__ x,
                const float* __restrict__ b1,
                const float* __restrict__ b2,
                const float* __restrict__ b3,
                float* __restrict__ out, int batch)
{
    const int tid  = threadIdx.x;
    const int w    = tid >> 5;
    const int lane = tid & 31;
    const int row0 = blockIdx.x * MTILE;
    const bool full = (row0 + MTILE) <= batch;

    // the 4 global rows this lane reads per stripe-pair
    const int r0 = row0 + w * 16 + (lane >> 2);     // stripe0 rows r0, r0+8
    const int r1 = r0 + 128;                        // stripe1 rows r1, r1+8
    const bool ok0a = full || (r0     < batch);
    const bool ok0b = full || (r0 + 8 < batch);
    const bool ok1a = full || (r1     < batch);
    const bool ok1b = full || (r1 + 8 < batch);

    const float* p0 = x + (size_t)r0 * IN_F + (lane & 3) * 2;
    const float* p1 = x + (size_t)r1 * IN_F + (lane & 3) * 2;

    float2 pf[8];
    uint32_t af[8];

    auto loadstep = [&](int s) {
        const int c = s * 16;
        const float2 z = make_float2(0.f, 0.f);
        pf[0] = ok0a ? __ldg((const float2*)(p0 + c))                : z;
        pf[1] = ok0b ? __ldg((const float2*)(p0 + c + 8 * IN_F))     : z;
        pf[2] = ok0a ? __ldg((const float2*)(p0 + c + 8))            : z;
        pf[3] = ok0b ? __ldg((const float2*)(p0 + c + 8 * IN_F + 8)) : z;
        pf[4] = ok1a ? __ldg((const float2*)(p1 + c))                : z;
        pf[5] = ok1b ? __ldg((const float2*)(p1 + c + 8 * IN_F))     : z;
        pf[6] = ok1a ? __ldg((const float2*)(p1 + c + 8))            : z;
        pf[7] = ok1b ? __ldg((const float2*)(p1 + c + 8 * IN_F + 8)) : z;
    };
    auto cvtstep = [&]() {
        #pragma unroll
        for (int i = 0; i < 8; ++i)
            af[i] = pkh(__float2half_rn(pf[i].x), __float2half_rn(pf[i].y));
    };

    float acc0[32], acc1[32];
    #pragma unroll
    for (int i = 0; i < 32; ++i) { acc0[i] = 0.f; acc1[i] = 0.f; }

    // ---- layer-1 GEMM: 48 k-steps, prefetch one step ahead ----
    loadstep(0);
    cvtstep();
    #pragma unroll 1
    for (int s = 0; s < NSTEP1; ++s) {
        if (s + 1 < NSTEP1) loadstep(s + 1);        // in flight during MMAs
        const uint4* wf = g_w1f + (size_t)s * 256 + lane;
        #pragma unroll
        for (int nb = 0; nb < 8; ++nb) {
            const uint4 f = __ldg(wf + nb * 32);
            mma16816(acc0 + nb * 4, af,     f.x, f.y);
            mma16816(acc0 + nb * 4, af,     f.z, f.w);
            mma16816(acc1 + nb * 4, af + 4, f.x, f.y);
            mma16816(acc1 + nb * 4, af + 4, f.z, f.w);
        }
        if (s + 1 < NSTEP1) cvtstep();              // data has arrived by now
    }

    // ---- h1 = relu(acc + b1), packed into A-fragment registers ----
    // hlo[st][nb] = rows g,    cols nb*8+(lane&3)*2 (+1)
    // hhi[st][nb] = rows g+8,  same cols
    uint32_t hlo0[8], hhi0[8], hlo1[8], hhi1[8];
    #pragma unroll
    for (int nb = 0; nb < 8; ++nb) {
        const int n = nb * 8 + (lane & 3) * 2;
        const float ba = __ldg(b1 + n), bb = __ldg(b1 + n + 1);
        hlo0[nb] = pkh(__float2half_rn(fmaxf(acc0[nb * 4 + 0] + ba, 0.f)),
                       __float2half_rn(fmaxf(acc0[nb * 4 + 1] + bb, 0.f)));
        hhi0[nb] = pkh(__float2half_rn(fmaxf(acc0[nb * 4 + 2] + ba, 0.f)),
                       __float2half_rn(fmaxf(acc0[nb * 4 + 3] + bb, 0.f)));
        hlo1[nb] = pkh(__float2half_rn(fmaxf(acc1[nb * 4 + 0] + ba, 0.f)),
                       __float2half_rn(fmaxf(acc1[nb * 4 + 1] + bb, 0.f)));
        hhi1[nb] = pkh(__float2half_rn(fmaxf(acc1[nb * 4 + 2] + ba, 0.f)),
                       __float2half_rn(fmaxf(acc1[nb * 4 + 3] + bb, 0.f)));
    }

    // ---- layer-2 GEMM (K=64), A straight from registers ----
    float ac20[32], ac21[32];
    #pragma unroll
    for (int i = 0; i < 32; ++i) { ac20[i] = 0.f; ac21[i] = 0.f; }
    #pragma unroll
    for (int s = 0; s < NSTEP2; ++s) {
        const uint32_t a0[4] = { hlo0[2 * s], hhi0[2 * s], hlo0[2 * s + 1], hhi0[2 * s + 1] };
        const uint32_t a1[4] = { hlo1[2 * s], hhi1[2 * s], hlo1[2 * s + 1], hhi1[2 * s + 1] };
        const uint4* wf = g_w2f + (size_t)s * 256 + lane;
        #pragma unroll
        for (int nb = 0; nb < 8; ++nb) {
            const uint4 f = __ldg(wf + nb * 32);
            mma16816(ac20 + nb * 4, a0, f.x, f.y);
            mma16816(ac20 + nb * 4, a0, f.z, f.w);
            mma16816(ac21 + nb * 4, a1, f.x, f.y);
            mma16816(ac21 + nb * 4, a1, f.z, f.w);
        }
    }

    // ---- epilogue: out = relu(ac2 + b2) . w3 + b3 ----
    {
        const float b3v = __ldg(b3);
        #pragma unroll
        for (int st = 0; st < 2; ++st) {
            const float* ac = st ? ac21 : ac20;
            float pA = 0.f, pB = 0.f;
            #pragma unroll
            for (int nb = 0; nb < 8; ++nb) {
                const int n = nb * 8 + (lane & 3) * 2;
                const float ba = __ldg(b2 + n), bb = __ldg(b2 + n + 1);
                const float wa = g_w3[n],       wb = g_w3[n + 1];
                pA += fmaxf(ac[nb * 4 + 0] + ba, 0.f) * wa
                    + fmaxf(ac[nb * 4 + 1] + bb, 0.f) * wb;
                pB += fmaxf(ac[nb * 4 + 2] + ba, 0.f) * wa
                    + fmaxf(ac[nb * 4 + 3] + bb, 0.f) * wb;
            }
            pA += __shfl_xor_sync(0xffffffffu, pA, 1);
            pA += __shfl_xor_sync(0xffffffffu, pA, 2);
            pB += __shfl_xor_sync(0xffffffffu, pB, 1);
            pB += __shfl_xor_sync(0xffffffffu, pB, 2);
            if ((lane & 3) == 0) {
                const int rA = row0 + st * 128 + w * 16 + (lane >> 2);
                if (rA < batch)     out[rA]     = pA + b3v;
                if (rA + 8 < batch) out[rA + 8] = pB + b3v;
            }
        }
    }
}

// ---------------------------------------------------------------------------
extern "C" void kernel_launch(void* const* d_in, const int* in_sizes, int n_in,
                              void* d_out, int out_size)
{
    const float* x    = (const float*)d_in[0];
    const int*   idx1 = (const int*)  d_in[1];
    const float* val1 = (const float*)d_in[2];
    const float* b1   = (const float*)d_in[3];
    const int*   idx2 = (const int*)  d_in[4];
    const float* val2 = (const float*)d_in[5];
    const float* b2   = (const float*)d_in[6];
    const int*   idx3 = (const int*)  d_in[7];
    const float* val3 = (const float*)d_in[8];
    const float* b3   = (const float*)d_in[9];

    const int nnz1  = in_sizes[1] / 2;
    const int nnz2  = in_sizes[4] / 2;
    const int nnz3  = in_sizes[7] / 2;
    const int batch = in_sizes[0] / IN_F;

    zero_kernel<<<64, 256>>>();
    scatter_kernel<<<32, 256>>>(idx1, val1, nnz1, idx2, val2, nnz2, idx3, val3, nnz3);
    pack_kernel<<<NSTEP1 + 1, THREADS>>>();

    const int blocks = (batch + MTILE - 1) / MTILE;
    mma_kernel<<<blocks, THREADS>>>(x, b1, b2, b3, (float*)d_out, batch);
}

// round 9
// speedup vs baseline: 1.5451x; 1.0967x over previous
#include <cuda_runtime.h>
#include <cuda_fp16.h>
#include <stdint.h>

#define IN_F    768
#define HID     64
#define MTILE   256
#define THREADS 256
#define NSTEP1  48           // 768/16 k-steps for layer 1 (= chunks)
#define NSTEP2  4            // 64/16 for layer 2
#define DEPTH   4            // cp.async ring depth
#define CHUNK_B 16384        // 256 rows x 16 K x 4B

// ---------------- device scratch (no allocations allowed) ----------------
__device__ float g_w1d[HID * IN_F];            // dense W1^T [n][k]
__device__ float g_w2d[HID * HID];             // dense W2^T [n][k]
__device__ uint4 g_w1f[NSTEP1 * 8 * 32];       // B-fragments: (main b0,b1, resid b0,b1)
__device__ uint4 g_w2f[NSTEP2 * 8 * 32];
__device__ float g_w3[HID];

static __device__ __forceinline__ void mma16816(float* d, const uint32_t* a,
                                                uint32_t b0, uint32_t b1) {
    asm volatile(
        "mma.sync.aligned.m16n8k16.row.col.f32.f16.f16.f32 "
        "{%0,%1,%2,%3}, {%4,%5,%6,%7}, {%8,%9}, {%0,%1,%2,%3};"
        : "+f"(d[0]), "+f"(d[1]), "+f"(d[2]), "+f"(d[3])
        : "r"(a[0]), "r"(a[1]), "r"(a[2]), "r"(a[3]), "r"(b0), "r"(b1));
}
static __device__ __forceinline__ uint32_t pkh(__half a, __half b) {
    __half2 h = __halves2half2(a, b);
    return *reinterpret_cast<uint32_t*>(&h);
}
static __device__ __forceinline__ uint32_t pk2(float2 v) {
    __half2 h = __floats2half2_rn(v.x, v.y);
    return *reinterpret_cast<uint32_t*>(&h);
}
static __device__ __forceinline__ void cp_async8(uint32_t daddr, const void* src, int srcsz) {
    asm volatile("cp.async.ca.shared.global [%0], [%1], 8, %2;"
                 :: "r"(daddr), "l"(src), "r"(srcsz) : "memory");
}
static __device__ __forceinline__ void cp_commit() {
    asm volatile("cp.async.commit_group;" ::: "memory");
}
template <int N>
static __device__ __forceinline__ void cp_wait() {
    asm volatile("cp.async.wait_group %0;" :: "n"(N) : "memory");
}

// ---------------- prep: zero -> scatter -> pack fragments (validated) ------
__global__ void zero_kernel() {
    const int t = blockIdx.x * blockDim.x + threadIdx.x;
    const int n = gridDim.x * blockDim.x;
    for (int i = t; i < HID * IN_F; i += n) g_w1d[i] = 0.f;
    for (int i = t; i < HID * HID;  i += n) g_w2d[i] = 0.f;
    for (int i = t; i < HID;        i += n) g_w3[i]  = 0.f;
}

__global__ void scatter_kernel(const int* __restrict__ idx1, const float* __restrict__ val1, int nnz1,
                               const int* __restrict__ idx2, const float* __restrict__ val2, int nnz2,
                               const int* __restrict__ idx3, const float* __restrict__ val3, int nnz3)
{
    const int t = blockIdx.x * blockDim.x + threadIdx.x;
    const int n = gridDim.x * blockDim.x;
    // idx layout [2,nnz]: rows then cols. dense is [n(col)][k(row)].
    for (int i = t; i < nnz1; i += n)
        atomicAdd(&g_w1d[idx1[nnz1 + i] * IN_F + idx1[i]], val1[i]);
    for (int i = t; i < nnz2; i += n)
        atomicAdd(&g_w2d[idx2[nnz2 + i] * HID + idx2[i]], val2[i]);
    for (int i = t; i < nnz3; i += n)
        atomicAdd(&g_w3[idx3[i]], val3[i]);
}

__global__ void pack_kernel() {
    const int tid = threadIdx.x;
    if (blockIdx.x < NSTEP1) {                 // one block per k-step of W1
        const int s    = blockIdx.x;
        const int nb   = tid >> 5;
        const int lane = tid & 31;
        const int k0 = s * 16 + (lane & 3) * 2;
        const int n  = nb * 8 + (lane >> 2);
        const float m0 = g_w1d[n * IN_F + k0];
        const float m1 = g_w1d[n * IN_F + k0 + 1];
        const float m2 = g_w1d[n * IN_F + k0 + 8];
        const float m3 = g_w1d[n * IN_F + k0 + 9];
        const __half h0 = __float2half_rn(m0), h1 = __float2half_rn(m1);
        const __half h2 = __float2half_rn(m2), h3 = __float2half_rn(m3);
        uint4 u;
        u.x = pkh(h0, h1);
        u.y = pkh(h2, h3);
        u.z = pkh(__float2half_rn(m0 - __half2float(h0)), __float2half_rn(m1 - __half2float(h1)));
        u.w = pkh(__float2half_rn(m2 - __half2float(h2)), __float2half_rn(m3 - __half2float(h3)));
        g_w1f[(s * 8 + nb) * 32 + lane] = u;
    } else {                                   // last block packs all of W2
        for (int j = tid; j < NSTEP2 * 8 * 32; j += THREADS) {
            const int s    = j >> 8;
            const int nb   = (j >> 5) & 7;
            const int lane = j & 31;
            const int k0 = s * 16 + (lane & 3) * 2;
            const int n  = nb * 8 + (lane >> 2);
            const float m0 = g_w2d[n * HID + k0];
            const float m1 = g_w2d[n * HID + k0 + 1];
            const float m2 = g_w2d[n * HID + k0 + 8];
            const float m3 = g_w2d[n * HID + k0 + 9];
            const __half h0 = __float2half_rn(m0), h1 = __float2half_rn(m1);
            const __half h2 = __float2half_rn(m2), h3 = __float2half_rn(m3);
            uint4 u;
            u.x = pkh(h0, h1);
            u.y = pkh(h2, h3);
            u.z = pkh(__float2half_rn(m0 - __half2float(h0)), __float2half_rn(m1 - __half2float(h1)));
            u.w = pkh(__float2half_rn(m2 - __half2float(h2)), __float2half_rn(m3 - __half2float(h3)));
            g_w2f[(s * 8 + nb) * 32 + lane] = u;
        }
    }
}

// ---------------------------------------------------------------------------
// Main kernel: x streamed fp32 via cp.async into a 4-deep ring (no staging
// registers, no exposed DRAM latency). A-fragments built by LDS.64 from fp32
// smem + F2FP pack (order identical to R8-verified path). h1 stays in
// registers; layer 2 + epilogue register-resident. 64KB smem -> 2 CTAs/SM.
// ---------------------------------------------------------------------------
extern __shared__ __align__(16) unsigned char smem[];

__global__ __launch_bounds__(THREADS, 2)
void mma_kernel(const float* __restrict__ x,
                const float* __restrict__ b1,
                const float* __restrict__ b2,
                const float* __restrict__ b3,
                float* __restrict__ out, int batch)
{
    uint32_t sb;
    asm("{ .reg .u64 t; cvta.to.shared.u64 t, %1; cvt.u32.u64 %0, t; }" : "=r"(sb) : "l"(smem));
    const int tid  = threadIdx.x;
    const int w    = tid >> 5;
    const int lane = tid & 31;
    const int row0 = blockIdx.x * MTILE;
    const bool full = (row0 + MTILE) <= batch;

    // ---- cp.async issue of one 16-K chunk (8 copies/thread, coalesced) ----
    const int crow = tid >> 3;        // 0..31 (row within a 32-row pass)
    const int cu   = tid & 7;         // 8B unit within the 16-float row piece
    auto issue = [&](int c) {
        const uint32_t dbase = sb + (uint32_t)(c & (DEPTH - 1)) * CHUNK_B;
        #pragma unroll
        for (int j = 0; j < 8; ++j) {
            const int row = j * 32 + crow;
            const int ok = (full || (row0 + row) < batch) ? 8 : 0;
            const float* src = x + (size_t)(row0 + row) * IN_F + c * 16 + cu * 2;
            cp_async8(dbase + (uint32_t)(row * 64 + cu * 8), src, ok);
        }
        cp_commit();
    };

    // A-fragment LDS geometry (order matches verified R8 af[0..3])
    const uint32_t a0 = (uint32_t)((w * 16 + (lane >> 2)) * 64 + (lane & 3) * 8);

    float acc0[32], acc1[32];
    #pragma unroll
    for (int i = 0; i < 32; ++i) { acc0[i] = 0.f; acc1[i] = 0.f; }

    // ---- prologue: 3 chunks in flight ----
    issue(0); issue(1); issue(2);

    // ---- layer-1 mainloop over 48 chunks (= k-steps) ----
    #pragma unroll 1
    for (int c = 0; c < NSTEP1; ++c) {
        cp_wait<2>();                 // chunk c complete (for this thread)
        __syncthreads();              // all threads' copies for chunk c visible

        const uint32_t xb = sb + (uint32_t)(c & (DEPTH - 1)) * CHUNK_B;
        uint32_t af[8];
        {
            float2 v;
            asm volatile("ld.shared.v2.f32 {%0,%1}, [%2];"       : "=f"(v.x), "=f"(v.y) : "r"(xb + a0));
            af[0] = pk2(v);
            asm volatile("ld.shared.v2.f32 {%0,%1}, [%2];"       : "=f"(v.x), "=f"(v.y) : "r"(xb + a0 + 512));
            af[1] = pk2(v);
            asm volatile("ld.shared.v2.f32 {%0,%1}, [%2];"       : "=f"(v.x), "=f"(v.y) : "r"(xb + a0 + 32));
            af[2] = pk2(v);
            asm volatile("ld.shared.v2.f32 {%0,%1}, [%2];"       : "=f"(v.x), "=f"(v.y) : "r"(xb + a0 + 544));
            af[3] = pk2(v);
            asm volatile("ld.shared.v2.f32 {%0,%1}, [%2];"       : "=f"(v.x), "=f"(v.y) : "r"(xb + a0 + 8192));
            af[4] = pk2(v);
            asm volatile("ld.shared.v2.f32 {%0,%1}, [%2];"       : "=f"(v.x), "=f"(v.y) : "r"(xb + a0 + 8704));
            af[5] = pk2(v);
            asm volatile("ld.shared.v2.f32 {%0,%1}, [%2];"       : "=f"(v.x), "=f"(v.y) : "r"(xb + a0 + 8224));
            af[6] = pk2(v);
            asm volatile("ld.shared.v2.f32 {%0,%1}, [%2];"       : "=f"(v.x), "=f"(v.y) : "r"(xb + a0 + 8736));
            af[7] = pk2(v);
        }

        const uint4* wf = g_w1f + (size_t)c * 256 + lane;
        #pragma unroll
        for (int nb = 0; nb < 8; ++nb) {
            const uint4 f = __ldg(wf + nb * 32);
            mma16816(acc0 + nb * 4, af,     f.x, f.y);
            mma16816(acc0 + nb * 4, af,     f.z, f.w);
            mma16816(acc1 + nb * 4, af + 4, f.x, f.y);
            mma16816(acc1 + nb * 4, af + 4, f.z, f.w);
        }

        __syncthreads();              // all warps done reading buf c before refill
        if (c + 3 < NSTEP1) issue(c + 3);
    }

    // ---- h1 = relu(acc + b1), packed into A-fragment registers (R8 path) ----
    uint32_t hlo0[8], hhi0[8], hlo1[8], hhi1[8];
    #pragma unroll
    for (int nb = 0; nb < 8; ++nb) {
        const int n = nb * 8 + (lane & 3) * 2;
        const float ba = __ldg(b1 + n), bb = __ldg(b1 + n + 1);
        hlo0[nb] = pkh(__float2half_rn(fmaxf(acc0[nb * 4 + 0] + ba, 0.f)),
                       __float2half_rn(fmaxf(acc0[nb * 4 + 1] + bb, 0.f)));
        hhi0[nb] = pkh(__float2half_rn(fmaxf(acc0[nb * 4 + 2] + ba, 0.f)),
                       __float2half_rn(fmaxf(acc0[nb * 4 + 3] + bb, 0.f)));
        hlo1[nb] = pkh(__float2half_rn(fmaxf(acc1[nb * 4 + 0] + ba, 0.f)),
                       __float2half_rn(fmaxf(acc1[nb * 4 + 1] + bb, 0.f)));
        hhi1[nb] = pkh(__float2half_rn(fmaxf(acc1[nb * 4 + 2] + ba, 0.f)),
                       __float2half_rn(fmaxf(acc1[nb * 4 + 3] + bb, 0.f)));
    }

    // ---- layer-2 GEMM (K=64), A straight from registers ----
    float ac20[32], ac21[32];
    #pragma unroll
    for (int i = 0; i < 32; ++i) { ac20[i] = 0.f; ac21[i] = 0.f; }
    #pragma unroll
    for (int s = 0; s < NSTEP2; ++s) {
        const uint32_t a0r[4] = { hlo0[2 * s], hhi0[2 * s], hlo0[2 * s + 1], hhi0[2 * s + 1] };
        const uint32_t a1r[4] = { hlo1[2 * s], hhi1[2 * s], hlo1[2 * s + 1], hhi1[2 * s + 1] };
        const uint4* wf = g_w2f + (size_t)s * 256 + lane;
        #pragma unroll
        for (int nb = 0; nb < 8; ++nb) {
            const uint4 f = __ldg(wf + nb * 32);
            mma16816(ac20 + nb * 4, a0r, f.x, f.y);
            mma16816(ac20 + nb * 4, a0r, f.z, f.w);
            mma16816(ac21 + nb * 4, a1r, f.x, f.y);
            mma16816(ac21 + nb * 4, a1r, f.z, f.w);
        }
    }

    // ---- epilogue: out = relu(ac2 + b2) . w3 + b3 ----
    {
        const float b3v = __ldg(b3);
        #pragma unroll
        for (int st = 0; st < 2; ++st) {
            const float* ac = st ? ac21 : ac20;
            float pA = 0.f, pB = 0.f;
            #pragma unroll
            for (int nb = 0; nb < 8; ++nb) {
                const int n = nb * 8 + (lane & 3) * 2;
                const float ba = __ldg(b2 + n), bb = __ldg(b2 + n + 1);
                const float wa = g_w3[n],       wb = g_w3[n + 1];
                pA += fmaxf(ac[nb * 4 + 0] + ba, 0.f) * wa
                    + fmaxf(ac[nb * 4 + 1] + bb, 0.f) * wb;
                pB += fmaxf(ac[nb * 4 + 2] + ba, 0.f) * wa
                    + fmaxf(ac[nb * 4 + 3] + bb, 0.f) * wb;
            }
            pA += __shfl_xor_sync(0xffffffffu, pA, 1);
            pA += __shfl_xor_sync(0xffffffffu, pA, 2);
            pB += __shfl_xor_sync(0xffffffffu, pB, 1);
            pB += __shfl_xor_sync(0xffffffffu, pB, 2);
            if ((lane & 3) == 0) {
                const int rA = row0 + st * 128 + w * 16 + (lane >> 2);
                if (rA < batch)     out[rA]     = pA + b3v;
                if (rA + 8 < batch) out[rA + 8] = pB + b3v;
            }
        }
    }
}

// ---------------------------------------------------------------------------
extern "C" void kernel_launch(void* const* d_in, const int* in_sizes, int n_in,
                              void* d_out, int out_size)
{
    const float* x    = (const float*)d_in[0];
    const int*   idx1 = (const int*)  d_in[1];
    const float* val1 = (const float*)d_in[2];
    const float* b1   = (const float*)d_in[3];
    const int*   idx2 = (const int*)  d_in[4];
    const float* val2 = (const float*)d_in[5];
    const float* b2   = (const float*)d_in[6];
    const int*   idx3 = (const int*)  d_in[7];
    const float* val3 = (const float*)d_in[8];
    const float* b3   = (const float*)d_in[9];

    const int nnz1  = in_sizes[1] / 2;
    const int nnz2  = in_sizes[4] / 2;
    const int nnz3  = in_sizes[7] / 2;
    const int batch = in_sizes[0] / IN_F;

    const int smem_bytes = DEPTH * CHUNK_B;   // 65536
    cudaFuncSetAttribute(mma_kernel, cudaFuncAttributeMaxDynamicSharedMemorySize, smem_bytes);

    zero_kernel<<<64, 256>>>();
    scatter_kernel<<<32, 256>>>(idx1, val1, nnz1, idx2, val2, nnz2, idx3, val3, nnz3);
    pack_kernel<<<NSTEP1 + 1, THREADS>>>();

    const int blocks = (batch + MTILE - 1) / MTILE;
    mma_kernel<<<blocks, THREADS, smem_bytes>>>(x, b1, b2, b3, (float*)d_out, batch);
}